// round 1
// baseline (speedup 1.0000x reference)
#include <cuda_runtime.h>
#include <math.h>

#define T 2048
#define D 1024
#define H 16
#define DH 64
#define NC 16
#define CS 128

// ---------------- scratch (no allocations allowed) ----------------
__device__ float g_xn[T*D];
__device__ float g_gate[T*D];
__device__ float g_qkv[T*3*D];
__device__ float g_Q[T*D];
__device__ float g_K[T*D];
__device__ float g_V[T*D];
__device__ float g_lkv[H*NC*DH*DH];
__device__ float g_lks[H*NC*DH];
__device__ float g_Spre[H*NC*DH*DH];
__device__ float g_zpre[H*NC*DH];
__device__ float g_attn[T*D];

// ---------------- f32x2 packed-FMA helpers (Blackwell FFMA2) ----------------
__device__ __forceinline__ unsigned long long pk2(float x, float y){
  unsigned long long r;
  asm("mov.b64 %0, {%1,%2};" : "=l"(r) : "f"(x), "f"(y));
  return r;
}
__device__ __forceinline__ void ff2(unsigned long long &d, unsigned long long a, unsigned long long b){
  asm("fma.rn.f32x2 %0, %1, %2, %0;" : "+l"(d) : "l"(a), "l"(b));
}
__device__ __forceinline__ void upk2(unsigned long long v, float &x, float &y){
  asm("mov.b64 {%0,%1}, %2;" : "=f"(x), "=f"(y) : "l"(v));
}

__device__ __forceinline__ float elu1f(float x){ return x > 0.f ? x + 1.f : expf(x); }

// ---------------- LayerNorm ----------------
__global__ void ln_kernel(const float* __restrict__ x, const float* __restrict__ g,
                          const float* __restrict__ b, float* __restrict__ xn)
{
  __shared__ float red[16];
  const int t = blockIdx.x;
  const int i = threadIdx.x;
  float4 xv = ((const float4*)(x + (size_t)t*D))[i];
  float s  = xv.x + xv.y + xv.z + xv.w;
  float s2 = xv.x*xv.x + xv.y*xv.y + xv.z*xv.z + xv.w*xv.w;
  const int lane = i & 31, w = i >> 5;
  #pragma unroll
  for (int o = 16; o; o >>= 1){
    s  += __shfl_xor_sync(0xffffffffu, s,  o);
    s2 += __shfl_xor_sync(0xffffffffu, s2, o);
  }
  if (lane == 0){ red[w] = s; red[8+w] = s2; }
  __syncthreads();
  if (i == 0){
    float a = 0.f, c = 0.f;
    #pragma unroll
    for (int k = 0; k < 8; k++){ a += red[k]; c += red[8+k]; }
    red[0] = a; red[8] = c;
  }
  __syncthreads();
  const float mu   = red[0] * (1.f / D);
  const float var  = red[8] * (1.f / D) - mu * mu;
  const float rstd = rsqrtf(var + 1e-5f);
  float4 gv = ((const float4*)g)[i];
  float4 bv = ((const float4*)b)[i];
  float4 o;
  o.x = (xv.x - mu) * rstd * gv.x + bv.x;
  o.y = (xv.y - mu) * rstd * gv.y + bv.y;
  o.z = (xv.z - mu) * rstd * gv.z + bv.z;
  o.w = (xv.w - mu) * rstd * gv.w + bv.w;
  ((float4*)(xn + (size_t)t*D))[i] = o;
}

// ---------------- SGEMM: C[M,N] = A[M,K] @ B[N,K]^T + bias, optional sigmoid ----------------
template<int SIG>
__global__ void __launch_bounds__(256) sgemm_kernel(const float* __restrict__ A,
    const float* __restrict__ B, const float* __restrict__ bias,
    float* __restrict__ C, int M, int N, int K)
{
  __shared__ __align__(16) float As[2][16][132];
  __shared__ __align__(16) float Bs[2][16][132];
  const int tid = threadIdx.x;
  const int tx = tid & 15, ty = tid >> 4;
  const int bm0 = blockIdx.y << 7, bn0 = blockIdx.x << 7;

  const int lr = tid >> 2;
  const int lc = (tid & 3) << 2;
  const float* Ap = A + (size_t)(bm0 + lr) * K + lc;
  const float* Bp = B + (size_t)(bn0 + lr) * K + lc;
  const size_t off64 = (size_t)64 * K;

  float4 ra0 = *(const float4*)(Ap);
  float4 ra1 = *(const float4*)(Ap + off64);
  float4 rb0 = *(const float4*)(Bp);
  float4 rb1 = *(const float4*)(Bp + off64);

  unsigned long long acc[8][4];
  #pragma unroll
  for (int i = 0; i < 8; i++)
    #pragma unroll
    for (int j = 0; j < 4; j++) acc[i][j] = 0ull;

  const int nk = K >> 4;

  #define STAGE(bufi) do { \
    As[bufi][lc+0][lr]    = ra0.x; As[bufi][lc+1][lr]    = ra0.y; \
    As[bufi][lc+2][lr]    = ra0.z; As[bufi][lc+3][lr]    = ra0.w; \
    As[bufi][lc+0][lr+64] = ra1.x; As[bufi][lc+1][lr+64] = ra1.y; \
    As[bufi][lc+2][lr+64] = ra1.z; As[bufi][lc+3][lr+64] = ra1.w; \
    Bs[bufi][lc+0][lr]    = rb0.x; Bs[bufi][lc+1][lr]    = rb0.y; \
    Bs[bufi][lc+2][lr]    = rb0.z; Bs[bufi][lc+3][lr]    = rb0.w; \
    Bs[bufi][lc+0][lr+64] = rb1.x; Bs[bufi][lc+1][lr+64] = rb1.y; \
    Bs[bufi][lc+2][lr+64] = rb1.z; Bs[bufi][lc+3][lr+64] = rb1.w; \
  } while(0)

  STAGE(0);
  __syncthreads();

  for (int kt = 0; kt < nk; kt++){
    const int cur = kt & 1;
    if (kt + 1 < nk){
      const float* Ap2 = Ap + (kt + 1) * 16;
      const float* Bp2 = Bp + (kt + 1) * 16;
      ra0 = *(const float4*)(Ap2);
      ra1 = *(const float4*)(Ap2 + off64);
      rb0 = *(const float4*)(Bp2);
      rb1 = *(const float4*)(Bp2 + off64);
    }
    #pragma unroll
    for (int k = 0; k < 16; k++){
      float4 a0 = *(const float4*)&As[cur][k][ty << 3];
      float4 a1 = *(const float4*)&As[cur][k][(ty << 3) + 4];
      float4 b0 = *(const float4*)&Bs[cur][k][tx << 3];
      float4 b1 = *(const float4*)&Bs[cur][k][(tx << 3) + 4];
      unsigned long long bp0 = pk2(b0.x, b0.y), bp1 = pk2(b0.z, b0.w);
      unsigned long long bp2 = pk2(b1.x, b1.y), bp3 = pk2(b1.z, b1.w);
      float av[8] = {a0.x, a0.y, a0.z, a0.w, a1.x, a1.y, a1.z, a1.w};
      #pragma unroll
      for (int i = 0; i < 8; i++){
        unsigned long long ap = pk2(av[i], av[i]);
        ff2(acc[i][0], ap, bp0);
        ff2(acc[i][1], ap, bp1);
        ff2(acc[i][2], ap, bp2);
        ff2(acc[i][3], ap, bp3);
      }
    }
    if (kt + 1 < nk){
      STAGE((kt + 1) & 1);
      __syncthreads();
    }
  }
  #undef STAGE

  const int col = bn0 + (tx << 3);
  float4 bv0 = *(const float4*)(bias + col);
  float4 bv1 = *(const float4*)(bias + col + 4);
  #pragma unroll
  for (int i = 0; i < 8; i++){
    const int row = bm0 + (ty << 3) + i;
    float o[8];
    upk2(acc[i][0], o[0], o[1]);
    upk2(acc[i][1], o[2], o[3]);
    upk2(acc[i][2], o[4], o[5]);
    upk2(acc[i][3], o[6], o[7]);
    o[0] += bv0.x; o[1] += bv0.y; o[2] += bv0.z; o[3] += bv0.w;
    o[4] += bv1.x; o[5] += bv1.y; o[6] += bv1.z; o[7] += bv1.w;
    if (SIG){
      #pragma unroll
      for (int j = 0; j < 8; j++) o[j] = 1.f / (1.f + expf(-o[j]));
    }
    float* cp = C + (size_t)row * N + col;
    *(float4*)cp       = make_float4(o[0], o[1], o[2], o[3]);
    *(float4*)(cp + 4) = make_float4(o[4], o[5], o[6], o[7]);
  }
}

// ---------------- gate-normalize + apply + elu+1 + head split ----------------
__global__ void prep_kernel(const float* __restrict__ gate, const float* __restrict__ qkv,
                            float* __restrict__ Q, float* __restrict__ K, float* __restrict__ V)
{
  __shared__ float red[8];
  const int t = blockIdx.x, i = threadIdx.x;
  float4 gv = ((const float4*)(gate + (size_t)t*D))[i];
  float s = gv.x + gv.y + gv.z + gv.w;
  const int lane = i & 31, w = i >> 5;
  #pragma unroll
  for (int o = 16; o; o >>= 1) s += __shfl_xor_sync(0xffffffffu, s, o);
  if (lane == 0) red[w] = s;
  __syncthreads();
  if (i == 0){
    float a = 0.f;
    #pragma unroll
    for (int k = 0; k < 8; k++) a += red[k];
    red[0] = a;
  }
  __syncthreads();
  const float inv = 1.f / (red[0] * (1.f / D) + 1e-5f);

  const float4* qrow = (const float4*)(qkv + (size_t)t * 3 * D);
  float4 qv = qrow[i], kv = qrow[i + 256], vv = qrow[i + 512];
  float4 qo, ko;
  qo.x = elu1f(qv.x * gv.x * inv); qo.y = elu1f(qv.y * gv.y * inv);
  qo.z = elu1f(qv.z * gv.z * inv); qo.w = elu1f(qv.w * gv.w * inv);
  ko.x = elu1f(kv.x * gv.x * inv); ko.y = elu1f(kv.y * gv.y * inv);
  ko.z = elu1f(kv.z * gv.z * inv); ko.w = elu1f(kv.w * gv.w * inv);

  const int h = i >> 4;
  const int dh = (i & 15) << 2;
  const size_t b4 = ((size_t)(h * T + t) * DH + dh) >> 2;
  ((float4*)Q)[b4] = qo;
  ((float4*)K)[b4] = ko;
  ((float4*)V)[b4] = vv;
}

// ---------------- per-(head,chunk) local K^T V and K column sums ----------------
__global__ void chunk_sums_kernel(const float* __restrict__ Kg, const float* __restrict__ Vg,
                                  float* __restrict__ lkv, float* __restrict__ lks)
{
  extern __shared__ float sm[];
  float* Ks = sm;            // CS x DH
  float* Vs = sm + CS * DH;  // CS x DH
  const int hc = blockIdx.x, h = hc >> 4, c = hc & 15;
  const float* Kc = Kg + (size_t)(h * T + c * CS) * DH;
  const float* Vc = Vg + (size_t)(h * T + c * CS) * DH;
  const int tid = threadIdx.x;
  for (int idx = tid; idx < CS * DH / 4; idx += 256){
    ((float4*)Ks)[idx] = ((const float4*)Kc)[idx];
    ((float4*)Vs)[idx] = ((const float4*)Vc)[idx];
  }
  __syncthreads();

  const int m = tid & 63;
  const int dg = tid >> 6;  // 0..3, each thread: 16 d's x 1 m
  float acc[16];
  #pragma unroll
  for (int i = 0; i < 16; i++) acc[i] = 0.f;
  for (int tt = 0; tt < CS; tt++){
    const float vv = Vs[tt * DH + m];
    #pragma unroll
    for (int i = 0; i < 16; i++)
      acc[i] += Ks[tt * DH + dg * 16 + i] * vv;
  }
  float* dst = lkv + (size_t)hc * DH * DH;
  #pragma unroll
  for (int i = 0; i < 16; i++)
    dst[(dg * 16 + i) * DH + m] = acc[i];

  if (tid < DH){
    float s = 0.f;
    for (int tt = 0; tt < CS; tt++) s += Ks[tt * DH + tid];
    lks[(size_t)hc * DH + tid] = s;
  }
}

// ---------------- exclusive prefix over chunks ----------------
__global__ void scan_kernel(const float* __restrict__ lkv, const float* __restrict__ lks,
                            float* __restrict__ Spre, float* __restrict__ zpre)
{
  const int h = blockIdx.x;
  for (int idx = threadIdx.x; idx < DH * DH; idx += blockDim.x){
    float acc = 0.f;
    for (int c = 0; c < NC; c++){
      const size_t o = (size_t)(h * NC + c) * DH * DH + idx;
      Spre[o] = acc;
      acc += lkv[o];
    }
  }
  for (int idx = threadIdx.x; idx < DH; idx += blockDim.x){
    float acc = 0.f;
    for (int c = 0; c < NC; c++){
      const size_t o = (size_t)(h * NC + c) * DH + idx;
      zpre[o] = acc;
      acc += lks[o];
    }
  }
}

// ---------------- per-(head,chunk) attention output ----------------
__global__ void attn_kernel(const float* __restrict__ Qg, const float* __restrict__ Kg,
                            const float* __restrict__ Vg, const float* __restrict__ Spre,
                            const float* __restrict__ zpre, float* __restrict__ Og)
{
  extern __shared__ float sm[];
  float* Qs  = sm;               // 128 x 65
  float* Ks  = Qs  + 128 * 65;   // 128 x 65 (later reused for V)
  float* As  = Ks  + 128 * 65;   // 128 x 130
  float* Sp  = As  + 128 * 130;  // 64 x 65
  float* zp  = Sp  + 64 * 65;    // 64
  float* dn  = zp  + 64;         // 128
  float* dnp = dn  + 128;        // 128 x 16 partial rowsums

  const int hc = blockIdx.x, h = hc >> 4, c = hc & 15;
  const int tid = threadIdx.x;
  const float* Qc = Qg + (size_t)(h * T + c * CS) * DH;
  const float* Kc = Kg + (size_t)(h * T + c * CS) * DH;

  for (int idx = tid; idx < CS * DH / 4; idx += 256){
    const int r = idx >> 4, c4 = (idx & 15) << 2;
    float4 q = ((const float4*)Qc)[idx];
    float4 k = ((const float4*)Kc)[idx];
    float* qd = Qs + r * 65 + c4;
    qd[0] = q.x; qd[1] = q.y; qd[2] = q.z; qd[3] = q.w;
    float* kd = Ks + r * 65 + c4;
    kd[0] = k.x; kd[1] = k.y; kd[2] = k.z; kd[3] = k.w;
  }
  const float* SpG = Spre + (size_t)hc * DH * DH;
  for (int idx = tid; idx < DH * DH; idx += 256)
    Sp[(idx >> 6) * 65 + (idx & 63)] = SpG[idx];
  if (tid < 64) zp[tid] = zpre[(size_t)hc * DH + tid];
  __syncthreads();

  // den init: q . z_pre
  if (tid < 128){
    float s = 0.f;
    #pragma unroll
    for (int d = 0; d < 64; d++) s += Qs[tid * 65 + d] * zp[d];
    dn[tid] = s;
  }
  __syncthreads();

  // phase 1: A = Q K^T with causal mask, track rowsums
  const int tx = tid & 15, ty = tid >> 4;
  {
    float acc[8][8];
    #pragma unroll
    for (int i = 0; i < 8; i++)
      #pragma unroll
      for (int j = 0; j < 8; j++) acc[i][j] = 0.f;
    for (int d = 0; d < 64; d++){
      float a[8], b[8];
      #pragma unroll
      for (int i = 0; i < 8; i++) a[i] = Qs[(ty * 8 + i) * 65 + d];
      #pragma unroll
      for (int j = 0; j < 8; j++) b[j] = Ks[(tx * 8 + j) * 65 + d];
      #pragma unroll
      for (int i = 0; i < 8; i++)
        #pragma unroll
        for (int j = 0; j < 8; j++)
          acc[i][j] += a[i] * b[j];
    }
    #pragma unroll
    for (int i = 0; i < 8; i++){
      const int r = ty * 8 + i;
      float rs = 0.f;
      #pragma unroll
      for (int j = 0; j < 8; j++){
        const int s_ = tx * 8 + j;
        const float v = (s_ <= r) ? acc[i][j] : 0.f;
        As[r * 130 + s_] = v;
        rs += v;
      }
      dnp[r * 16 + tx] = rs;
    }
  }
  __syncthreads();

  // load V over K buffer; finalize den (deterministic reduce)
  {
    const float* Vc = Vg + (size_t)(h * T + c * CS) * DH;
    for (int idx = tid; idx < CS * DH / 4; idx += 256){
      const int r = idx >> 4, c4 = (idx & 15) << 2;
      float4 v = ((const float4*)Vc)[idx];
      float* vd = Ks + r * 65 + c4;
      vd[0] = v.x; vd[1] = v.y; vd[2] = v.z; vd[3] = v.w;
    }
    if (tid < 128){
      float s = dn[tid];
      #pragma unroll
      for (int xx = 0; xx < 16; xx++) s += dnp[tid * 16 + xx];
      dn[tid] = s + 1e-5f;
    }
  }
  __syncthreads();

  // phase 2: out = (A @ V + Q @ S_pre) / den
  {
    float acc2[8][4];
    #pragma unroll
    for (int i = 0; i < 8; i++)
      #pragma unroll
      for (int j = 0; j < 4; j++) acc2[i][j] = 0.f;
    const int m0 = tx * 4, r0 = ty * 8;
    for (int s = 0; s < 128; s++){
      float vv[4];
      #pragma unroll
      for (int jj = 0; jj < 4; jj++) vv[jj] = Ks[s * 65 + m0 + jj];
      #pragma unroll
      for (int i = 0; i < 8; i++){
        const float av = As[(r0 + i) * 130 + s];
        #pragma unroll
        for (int jj = 0; jj < 4; jj++) acc2[i][jj] += av * vv[jj];
      }
    }
    for (int d = 0; d < 64; d++){
      float sp[4];
      #pragma unroll
      for (int jj = 0; jj < 4; jj++) sp[jj] = Sp[d * 65 + m0 + jj];
      #pragma unroll
      for (int i = 0; i < 8; i++){
        const float qv = Qs[(r0 + i) * 65 + d];
        #pragma unroll
        for (int jj = 0; jj < 4; jj++) acc2[i][jj] += qv * sp[jj];
      }
    }
    float* Orow = Og + (size_t)(c * CS) * D + h * DH;
    #pragma unroll
    for (int i = 0; i < 8; i++){
      const float inv = 1.f / dn[r0 + i];
      float4 o = make_float4(acc2[i][0] * inv, acc2[i][1] * inv,
                             acc2[i][2] * inv, acc2[i][3] * inv);
      *(float4*)&Orow[(size_t)(r0 + i) * D + m0] = o;
    }
  }
}

// ---------------- launch ----------------
extern "C" void kernel_launch(void* const* d_in, const int* in_sizes, int n_in,
                              void* d_out, int out_size)
{
  (void)in_sizes; (void)n_in; (void)out_size;
  const float* x      = (const float*)d_in[0];
  const float* ln_g   = (const float*)d_in[1];
  const float* ln_b   = (const float*)d_in[2];
  const float* qkv_w  = (const float*)d_in[3];
  const float* qkv_b  = (const float*)d_in[4];
  const float* gate_w = (const float*)d_in[5];
  const float* gate_b = (const float*)d_in[6];
  const float* proj_w = (const float*)d_in[7];
  const float* proj_b = (const float*)d_in[8];
  float* out = (float*)d_out;

  float *xn, *gate, *qkv, *Q, *K, *V, *lkv, *lks, *Spre, *zpre, *attn;
  cudaGetSymbolAddress((void**)&xn,   g_xn);
  cudaGetSymbolAddress((void**)&gate, g_gate);
  cudaGetSymbolAddress((void**)&qkv,  g_qkv);
  cudaGetSymbolAddress((void**)&Q,    g_Q);
  cudaGetSymbolAddress((void**)&K,    g_K);
  cudaGetSymbolAddress((void**)&V,    g_V);
  cudaGetSymbolAddress((void**)&lkv,  g_lkv);
  cudaGetSymbolAddress((void**)&lks,  g_lks);
  cudaGetSymbolAddress((void**)&Spre, g_Spre);
  cudaGetSymbolAddress((void**)&zpre, g_zpre);
  cudaGetSymbolAddress((void**)&attn, g_attn);

  const int CHUNK_SMEM = 2 * CS * DH * 4;                       // 65536
  const int ATTN_SMEM  = (128*65 + 128*65 + 128*130 + 64*65 + 64 + 128 + 128*16) * 4; // 158720
  cudaFuncSetAttribute(chunk_sums_kernel, cudaFuncAttributeMaxDynamicSharedMemorySize, CHUNK_SMEM);
  cudaFuncSetAttribute(attn_kernel,       cudaFuncAttributeMaxDynamicSharedMemorySize, ATTN_SMEM);

  ln_kernel<<<T, 256>>>(x, ln_g, ln_b, xn);
  sgemm_kernel<1><<<dim3(D / 128, T / 128), 256>>>(x,  gate_w, gate_b, gate, T, D,     D);
  sgemm_kernel<0><<<dim3(3 * D / 128, T / 128), 256>>>(xn, qkv_w, qkv_b, qkv, T, 3 * D, D);
  prep_kernel<<<T, 256>>>(gate, qkv, Q, K, V);
  chunk_sums_kernel<<<H * NC, 256, CHUNK_SMEM>>>(K, V, lkv, lks);
  scan_kernel<<<H, 256>>>(lkv, lks, Spre, zpre);
  attn_kernel<<<H * NC, 256, ATTN_SMEM>>>(Q, K, V, Spre, zpre, attn);
  sgemm_kernel<0><<<dim3(D / 128, T / 128), 256>>>(attn, proj_w, proj_b, out, T, D, D);
}

// round 3
// speedup vs baseline: 1.7086x; 1.7086x over previous
#include <cuda_runtime.h>
#include <cuda_bf16.h>
#include <cstdint>
#include <math.h>

#define T 2048
#define D 1024
#define H 16
#define DH 64
#define NC 16
#define CS 128
#define GK 1024

// ---------------- scratch (no allocations allowed) ----------------
__device__ float g_gate[T*D];
__device__ float g_qkv[T*3*D];
__device__ float g_Q[T*D];
__device__ float g_K[T*D];
__device__ float g_V[T*D];
__device__ float g_lkv[H*NC*DH*DH];
__device__ float g_lks[H*NC*DH];
__device__ float g_Spre[H*NC*DH*DH];
__device__ float g_zpre[H*NC*DH];

// bf16 hi/lo splits
__device__ __nv_bfloat16 g_xh[T*D],  g_xl[T*D];
__device__ __nv_bfloat16 g_xnh[T*D], g_xnl[T*D];
__device__ __nv_bfloat16 g_ah[T*D],  g_al[T*D];
__device__ __nv_bfloat16 g_qwh[3*D*D], g_qwl[3*D*D];
__device__ __nv_bfloat16 g_gwh[D*D],   g_gwl[D*D];
__device__ __nv_bfloat16 g_pwh[D*D],   g_pwl[D*D];

// ---------------- helpers ----------------
__device__ __forceinline__ uint32_t smem_u32(const void* p){
  uint32_t a;
  asm("{ .reg .u64 t; cvta.to.shared.u64 t, %1; cvt.u32.u64 %0, t; }" : "=r"(a) : "l"(p));
  return a;
}
__device__ __forceinline__ float elu1f(float x){ return x > 0.f ? x + 1.f : expf(x); }
__device__ __forceinline__ void split1(float v, __nv_bfloat16 &h, __nv_bfloat16 &l){
  h = __float2bfloat16(v);
  l = __float2bfloat16(v - __bfloat162float(h));
}

__device__ __forceinline__ void ldsm_x4(uint32_t* r, uint32_t addr){
  asm volatile("ldmatrix.sync.aligned.m8n8.x4.shared.b16 {%0,%1,%2,%3}, [%4];"
    : "=r"(r[0]), "=r"(r[1]), "=r"(r[2]), "=r"(r[3]) : "r"(addr));
}
__device__ __forceinline__ void mma_bf16(float* c, const uint32_t* a, const uint32_t* b){
  asm volatile(
    "mma.sync.aligned.m16n8k16.row.col.f32.bf16.bf16.f32 "
    "{%0,%1,%2,%3},{%4,%5,%6,%7},{%8,%9},{%0,%1,%2,%3};"
    : "+f"(c[0]), "+f"(c[1]), "+f"(c[2]), "+f"(c[3])
    : "r"(a[0]), "r"(a[1]), "r"(a[2]), "r"(a[3]), "r"(b[0]), "r"(b[1]));
}
__device__ __forceinline__ void cp16(uint32_t smem, const void* gmem){
  asm volatile("cp.async.cg.shared.global [%0], [%1], 16;" :: "r"(smem), "l"(gmem));
}
__device__ __forceinline__ void cp_commit(){
  asm volatile("cp.async.commit_group;" ::: "memory");
}
template<int N>
__device__ __forceinline__ void cp_wait(){
  asm volatile("cp.async.wait_group %0;" :: "n"(N) : "memory");
}

// ---------------- split fp32 -> bf16 hi/lo ----------------
__global__ void split_kernel(const float* __restrict__ src,
                             __nv_bfloat16* __restrict__ h,
                             __nv_bfloat16* __restrict__ l, int n4)
{
  int i = blockIdx.x * 256 + threadIdx.x;
  if (i >= n4) return;
  float4 v = ((const float4*)src)[i];
  __nv_bfloat16 hv[4], lv[4];
  split1(v.x, hv[0], lv[0]); split1(v.y, hv[1], lv[1]);
  split1(v.z, hv[2], lv[2]); split1(v.w, hv[3], lv[3]);
  ((__nv_bfloat162*)h)[i*2]   = __nv_bfloat162(hv[0], hv[1]);
  ((__nv_bfloat162*)h)[i*2+1] = __nv_bfloat162(hv[2], hv[3]);
  ((__nv_bfloat162*)l)[i*2]   = __nv_bfloat162(lv[0], lv[1]);
  ((__nv_bfloat162*)l)[i*2+1] = __nv_bfloat162(lv[2], lv[3]);
}

// ---------------- LayerNorm -> bf16 hi/lo ----------------
__global__ void ln_kernel(const float* __restrict__ x, const float* __restrict__ g,
                          const float* __restrict__ b,
                          __nv_bfloat16* __restrict__ xnh, __nv_bfloat16* __restrict__ xnl)
{
  __shared__ float red[16];
  const int t = blockIdx.x;
  const int i = threadIdx.x;
  float4 xv = ((const float4*)(x + (size_t)t*D))[i];
  float s  = xv.x + xv.y + xv.z + xv.w;
  float s2 = xv.x*xv.x + xv.y*xv.y + xv.z*xv.z + xv.w*xv.w;
  const int lane = i & 31, w = i >> 5;
  #pragma unroll
  for (int o = 16; o; o >>= 1){
    s  += __shfl_xor_sync(0xffffffffu, s,  o);
    s2 += __shfl_xor_sync(0xffffffffu, s2, o);
  }
  if (lane == 0){ red[w] = s; red[8+w] = s2; }
  __syncthreads();
  if (i == 0){
    float a = 0.f, c = 0.f;
    #pragma unroll
    for (int k = 0; k < 8; k++){ a += red[k]; c += red[8+k]; }
    red[0] = a; red[8] = c;
  }
  __syncthreads();
  const float mu   = red[0] * (1.f / D);
  const float var  = red[8] * (1.f / D) - mu * mu;
  const float rstd = rsqrtf(var + 1e-5f);
  float4 gv = ((const float4*)g)[i];
  float4 bv = ((const float4*)b)[i];
  float o[4];
  o[0] = (xv.x - mu) * rstd * gv.x + bv.x;
  o[1] = (xv.y - mu) * rstd * gv.y + bv.y;
  o[2] = (xv.z - mu) * rstd * gv.z + bv.z;
  o[3] = (xv.w - mu) * rstd * gv.w + bv.w;
  __nv_bfloat16 hv[4], lv[4];
  #pragma unroll
  for (int k = 0; k < 4; k++) split1(o[k], hv[k], lv[k]);
  const size_t base2 = ((size_t)t*D >> 1) + i*2;
  ((__nv_bfloat162*)xnh)[base2]   = __nv_bfloat162(hv[0], hv[1]);
  ((__nv_bfloat162*)xnh)[base2+1] = __nv_bfloat162(hv[2], hv[3]);
  ((__nv_bfloat162*)xnl)[base2]   = __nv_bfloat162(lv[0], lv[1]);
  ((__nv_bfloat162*)xnl)[base2+1] = __nv_bfloat162(lv[2], lv[3]);
}

// ---------------- HMMA GEMM: C[2048,N] = A[2048,1024] @ B[N,1024]^T ----------------
// 3-term bf16 split: C = Ah Bh + Ah Bl + Al Bh (fp32 accum).
// Block tile 128x128, BK=32, 8 warps of 64x32, cp.async double buffer.
#define PITCH 80          // bytes per SMEM row (64B data + 16B pad)
#define ARR   (128*PITCH) // 10240 B per array
#define STAGE (4*ARR)     // Ah,Al,Bh,Bl
#define NKT   (GK/32)     // 32 k-tiles

__device__ __forceinline__ void gemm_load_stage(uint32_t sbase,
    const __nv_bfloat16* Ah, const __nv_bfloat16* Al,
    const __nv_bfloat16* Bh, const __nv_bfloat16* Bl,
    int kt, int tid)
{
  const int koff = kt * 32;
  const __nv_bfloat16* srcs[4] = {Ah, Al, Bh, Bl};
  #pragma unroll
  for (int arr = 0; arr < 4; arr++){
    const __nv_bfloat16* s = srcs[arr] + koff;
    #pragma unroll
    for (int it = 0; it < 2; it++){
      const int within = tid + it * 256;      // 0..511
      const int row = within >> 2, c16 = within & 3;
      cp16(sbase + arr*ARR + row*PITCH + c16*16,
           s + (size_t)row * GK + c16*8);
    }
  }
}

template<int SIG>
__global__ void __launch_bounds__(256, 1)
hmma_gemm_kernel(const __nv_bfloat16* __restrict__ Ah, const __nv_bfloat16* __restrict__ Al,
                 const __nv_bfloat16* __restrict__ Bh, const __nv_bfloat16* __restrict__ Bl,
                 const float* __restrict__ bias, float* __restrict__ C, int N)
{
  extern __shared__ __align__(128) char sm[];
  const uint32_t sb = smem_u32(sm);
  const int tid = threadIdx.x;
  const int wid = tid >> 5, lane = tid & 31;
  const int wm = wid & 1, wn = wid >> 1;
  const int m0w = wm * 64, n0w = wn * 32;
  const int bm0 = blockIdx.y << 7, bn0 = blockIdx.x << 7;

  const __nv_bfloat16* pAh = Ah + (size_t)bm0 * GK;
  const __nv_bfloat16* pAl = Al + (size_t)bm0 * GK;
  const __nv_bfloat16* pBh = Bh + (size_t)bn0 * GK;
  const __nv_bfloat16* pBl = Bl + (size_t)bn0 * GK;

  float acc[4][4][4];
  #pragma unroll
  for (int i = 0; i < 4; i++)
    #pragma unroll
    for (int j = 0; j < 4; j++)
      #pragma unroll
      for (int q = 0; q < 4; q++) acc[i][j][q] = 0.f;

  // ldmatrix per-lane offsets
  const int rowA = lane & 15;
  const uint32_t colA = (lane >> 4) << 4;                 // 0 or 16 bytes
  const int rowB = (lane & 7) + (((lane >> 4) & 1) << 3); // 0..15
  const uint32_t colB = ((lane >> 3) & 1) << 4;           // 0 or 16 bytes

  gemm_load_stage(sb, pAh, pAl, pBh, pBl, 0, tid);
  cp_commit();

  for (int kt = 0; kt < NKT; kt++){
    if (kt + 1 < NKT){
      gemm_load_stage(sb + ((kt + 1) & 1) * STAGE, pAh, pAl, pBh, pBl, kt + 1, tid);
      cp_commit();
      cp_wait<1>();
    } else {
      cp_wait<0>();
    }
    __syncthreads();

    const uint32_t st = sb + (kt & 1) * STAGE;
    const uint32_t aBaseH = st           + (m0w + rowA) * PITCH + colA;
    const uint32_t aBaseL = st + ARR     + (m0w + rowA) * PITCH + colA;
    const uint32_t bBaseH = st + 2*ARR   + (n0w + rowB) * PITCH + colB;
    const uint32_t bBaseL = st + 3*ARR   + (n0w + rowB) * PITCH + colB;

    #pragma unroll
    for (int ks = 0; ks < 2; ks++){
      const uint32_t kb = ks * 32;
      uint32_t a_h[4][4], a_l[4][4], b_h[4][2], b_l[4][2];
      #pragma unroll
      for (int mi = 0; mi < 4; mi++){
        ldsm_x4(a_h[mi], aBaseH + mi*16*PITCH + kb);
        ldsm_x4(a_l[mi], aBaseL + mi*16*PITCH + kb);
      }
      #pragma unroll
      for (int p = 0; p < 2; p++){
        uint32_t r[4];
        ldsm_x4(r, bBaseH + p*16*PITCH + kb);
        b_h[2*p][0] = r[0]; b_h[2*p][1] = r[1];
        b_h[2*p+1][0] = r[2]; b_h[2*p+1][1] = r[3];
        ldsm_x4(r, bBaseL + p*16*PITCH + kb);
        b_l[2*p][0] = r[0]; b_l[2*p][1] = r[1];
        b_l[2*p+1][0] = r[2]; b_l[2*p+1][1] = r[3];
      }
      // term 1: Ah*Bh
      #pragma unroll
      for (int mi = 0; mi < 4; mi++)
        #pragma unroll
        for (int nj = 0; nj < 4; nj++)
          mma_bf16(acc[mi][nj], a_h[mi], b_h[nj]);
      // term 2: Ah*Bl
      #pragma unroll
      for (int mi = 0; mi < 4; mi++)
        #pragma unroll
        for (int nj = 0; nj < 4; nj++)
          mma_bf16(acc[mi][nj], a_h[mi], b_l[nj]);
      // term 3: Al*Bh
      #pragma unroll
      for (int mi = 0; mi < 4; mi++)
        #pragma unroll
        for (int nj = 0; nj < 4; nj++)
          mma_bf16(acc[mi][nj], a_l[mi], b_h[nj]);
    }
    __syncthreads();
  }

  // epilogue
  const int g = lane >> 2, t4 = lane & 3;
  #pragma unroll
  for (int mi = 0; mi < 4; mi++){
    #pragma unroll
    for (int nj = 0; nj < 4; nj++){
      const int row = bm0 + m0w + mi*16 + g;
      const int col = bn0 + n0w + nj*8 + t4*2;
      float b0 = bias[col], b1 = bias[col+1];
      float o0 = acc[mi][nj][0] + b0, o1 = acc[mi][nj][1] + b1;
      float o2 = acc[mi][nj][2] + b0, o3 = acc[mi][nj][3] + b1;
      if (SIG){
        o0 = 1.f / (1.f + expf(-o0)); o1 = 1.f / (1.f + expf(-o1));
        o2 = 1.f / (1.f + expf(-o2)); o3 = 1.f / (1.f + expf(-o3));
      }
      *(float2*)(C + (size_t)row * N + col)       = make_float2(o0, o1);
      *(float2*)(C + (size_t)(row + 8) * N + col) = make_float2(o2, o3);
    }
  }
}

// ---------------- gate-normalize + apply + elu+1 + head split ----------------
__global__ void prep_kernel(const float* __restrict__ gate, const float* __restrict__ qkv,
                            float* __restrict__ Q, float* __restrict__ K, float* __restrict__ V)
{
  __shared__ float red[8];
  const int t = blockIdx.x, i = threadIdx.x;
  float4 gv = ((const float4*)(gate + (size_t)t*D))[i];
  float s = gv.x + gv.y + gv.z + gv.w;
  const int lane = i & 31, w = i >> 5;
  #pragma unroll
  for (int o = 16; o; o >>= 1) s += __shfl_xor_sync(0xffffffffu, s, o);
  if (lane == 0) red[w] = s;
  __syncthreads();
  if (i == 0){
    float a = 0.f;
    #pragma unroll
    for (int k = 0; k < 8; k++) a += red[k];
    red[0] = a;
  }
  __syncthreads();
  const float inv = 1.f / (red[0] * (1.f / D) + 1e-5f);

  const float4* qrow = (const float4*)(qkv + (size_t)t * 3 * D);
  float4 qv = qrow[i], kv = qrow[i + 256], vv = qrow[i + 512];
  float4 qo, ko;
  qo.x = elu1f(qv.x * gv.x * inv); qo.y = elu1f(qv.y * gv.y * inv);
  qo.z = elu1f(qv.z * gv.z * inv); qo.w = elu1f(qv.w * gv.w * inv);
  ko.x = elu1f(kv.x * gv.x * inv); ko.y = elu1f(kv.y * gv.y * inv);
  ko.z = elu1f(kv.z * gv.z * inv); ko.w = elu1f(kv.w * gv.w * inv);

  const int h = i >> 4;
  const int dh = (i & 15) << 2;
  const size_t b4 = ((size_t)(h * T + t) * DH + dh) >> 2;
  ((float4*)Q)[b4] = qo;
  ((float4*)K)[b4] = ko;
  ((float4*)V)[b4] = vv;
}

// ---------------- per-(head,chunk) local K^T V and K column sums ----------------
__global__ void chunk_sums_kernel(const float* __restrict__ Kg, const float* __restrict__ Vg,
                                  float* __restrict__ lkv, float* __restrict__ lks)
{
  extern __shared__ float smf[];
  float* Ks = smf;
  float* Vs = smf + CS * DH;
  const int hc = blockIdx.x, h = hc >> 4, c = hc & 15;
  const float* Kc = Kg + (size_t)(h * T + c * CS) * DH;
  const float* Vc = Vg + (size_t)(h * T + c * CS) * DH;
  const int tid = threadIdx.x;
  for (int idx = tid; idx < CS * DH / 4; idx += 256){
    ((float4*)Ks)[idx] = ((const float4*)Kc)[idx];
    ((float4*)Vs)[idx] = ((const float4*)Vc)[idx];
  }
  __syncthreads();

  const int m = tid & 63;
  const int dg = tid >> 6;
  float acc[16];
  #pragma unroll
  for (int i = 0; i < 16; i++) acc[i] = 0.f;
  for (int tt = 0; tt < CS; tt++){
    const float vv = Vs[tt * DH + m];
    #pragma unroll
    for (int i = 0; i < 16; i++)
      acc[i] += Ks[tt * DH + dg * 16 + i] * vv;
  }
  float* dst = lkv + (size_t)hc * DH * DH;
  #pragma unroll
  for (int i = 0; i < 16; i++)
    dst[(dg * 16 + i) * DH + m] = acc[i];

  if (tid < DH){
    float s = 0.f;
    for (int tt = 0; tt < CS; tt++) s += Ks[tt * DH + tid];
    lks[(size_t)hc * DH + tid] = s;
  }
}

// ---------------- exclusive prefix over chunks ----------------
__global__ void scan_kernel(const float* __restrict__ lkv, const float* __restrict__ lks,
                            float* __restrict__ Spre, float* __restrict__ zpre)
{
  const int h = blockIdx.x;
  for (int idx = threadIdx.x; idx < DH * DH; idx += blockDim.x){
    float acc = 0.f;
    for (int c = 0; c < NC; c++){
      const size_t o = (size_t)(h * NC + c) * DH * DH + idx;
      Spre[o] = acc;
      acc += lkv[o];
    }
  }
  for (int idx = threadIdx.x; idx < DH; idx += blockDim.x){
    float acc = 0.f;
    for (int c = 0; c < NC; c++){
      const size_t o = (size_t)(h * NC + c) * DH + idx;
      zpre[o] = acc;
      acc += lks[o];
    }
  }
}

// ---------------- per-(head,chunk) attention output -> bf16 hi/lo ----------------
__global__ void attn_kernel(const float* __restrict__ Qg, const float* __restrict__ Kg,
                            const float* __restrict__ Vg, const float* __restrict__ Spre,
                            const float* __restrict__ zpre,
                            __nv_bfloat16* __restrict__ Oh, __nv_bfloat16* __restrict__ Ol)
{
  extern __shared__ float smf[];
  float* Qs  = smf;              // 128 x 65
  float* Ks  = Qs  + 128 * 65;   // 128 x 65 (later reused for V)
  float* As  = Ks  + 128 * 65;   // 128 x 130
  float* Sp  = As  + 128 * 130;  // 64 x 65
  float* zp  = Sp  + 64 * 65;    // 64
  float* dn  = zp  + 64;         // 128
  float* dnp = dn  + 128;        // 128 x 16

  const int hc = blockIdx.x, h = hc >> 4, c = hc & 15;
  const int tid = threadIdx.x;
  const float* Qc = Qg + (size_t)(h * T + c * CS) * DH;
  const float* Kc = Kg + (size_t)(h * T + c * CS) * DH;

  for (int idx = tid; idx < CS * DH / 4; idx += 256){
    const int r = idx >> 4, c4 = (idx & 15) << 2;
    float4 q = ((const float4*)Qc)[idx];
    float4 k = ((const float4*)Kc)[idx];
    float* qd = Qs + r * 65 + c4;
    qd[0] = q.x; qd[1] = q.y; qd[2] = q.z; qd[3] = q.w;
    float* kd = Ks + r * 65 + c4;
    kd[0] = k.x; kd[1] = k.y; kd[2] = k.z; kd[3] = k.w;
  }
  const float* SpG = Spre + (size_t)hc * DH * DH;
  for (int idx = tid; idx < DH * DH; idx += 256)
    Sp[(idx >> 6) * 65 + (idx & 63)] = SpG[idx];
  if (tid < 64) zp[tid] = zpre[(size_t)hc * DH + tid];
  __syncthreads();

  if (tid < 128){
    float s = 0.f;
    #pragma unroll
    for (int d = 0; d < 64; d++) s += Qs[tid * 65 + d] * zp[d];
    dn[tid] = s;
  }
  __syncthreads();

  const int tx = tid & 15, ty = tid >> 4;
  {
    float acc[8][8];
    #pragma unroll
    for (int i = 0; i < 8; i++)
      #pragma unroll
      for (int j = 0; j < 8; j++) acc[i][j] = 0.f;
    for (int d = 0; d < 64; d++){
      float a[8], b[8];
      #pragma unroll
      for (int i = 0; i < 8; i++) a[i] = Qs[(ty * 8 + i) * 65 + d];
      #pragma unroll
      for (int j = 0; j < 8; j++) b[j] = Ks[(tx * 8 + j) * 65 + d];
      #pragma unroll
      for (int i = 0; i < 8; i++)
        #pragma unroll
        for (int j = 0; j < 8; j++)
          acc[i][j] += a[i] * b[j];
    }
    #pragma unroll
    for (int i = 0; i < 8; i++){
      const int r = ty * 8 + i;
      float rs = 0.f;
      #pragma unroll
      for (int j = 0; j < 8; j++){
        const int s_ = tx * 8 + j;
        const float v = (s_ <= r) ? acc[i][j] : 0.f;
        As[r * 130 + s_] = v;
        rs += v;
      }
      dnp[r * 16 + tx] = rs;
    }
  }
  __syncthreads();

  {
    const float* Vc = Vg + (size_t)(h * T + c * CS) * DH;
    for (int idx = tid; idx < CS * DH / 4; idx += 256){
      const int r = idx >> 4, c4 = (idx & 15) << 2;
      float4 v = ((const float4*)Vc)[idx];
      float* vd = Ks + r * 65 + c4;
      vd[0] = v.x; vd[1] = v.y; vd[2] = v.z; vd[3] = v.w;
    }
    if (tid < 128){
      float s = dn[tid];
      #pragma unroll
      for (int xx = 0; xx < 16; xx++) s += dnp[tid * 16 + xx];
      dn[tid] = s + 1e-5f;
    }
  }
  __syncthreads();

  {
    float acc2[8][4];
    #pragma unroll
    for (int i = 0; i < 8; i++)
      #pragma unroll
      for (int j = 0; j < 4; j++) acc2[i][j] = 0.f;
    const int m0 = tx * 4, r0 = ty * 8;
    for (int s = 0; s < 128; s++){
      float vv[4];
      #pragma unroll
      for (int jj = 0; jj < 4; jj++) vv[jj] = Ks[s * 65 + m0 + jj];
      #pragma unroll
      for (int i = 0; i < 8; i++){
        const float av = As[(r0 + i) * 130 + s];
        #pragma unroll
        for (int jj = 0; jj < 4; jj++) acc2[i][jj] += av * vv[jj];
      }
    }
    for (int d = 0; d < 64; d++){
      float sp[4];
      #pragma unroll
      for (int jj = 0; jj < 4; jj++) sp[jj] = Sp[d * 65 + m0 + jj];
      #pragma unroll
      for (int i = 0; i < 8; i++){
        const float qv = Qs[(r0 + i) * 65 + d];
        #pragma unroll
        for (int jj = 0; jj < 4; jj++) acc2[i][jj] += qv * sp[jj];
      }
    }
    const size_t obase = (size_t)(c * CS) * D + h * DH;
    #pragma unroll
    for (int i = 0; i < 8; i++){
      const float inv = 1.f / dn[r0 + i];
      __nv_bfloat16 hv[4], lv[4];
      #pragma unroll
      for (int jj = 0; jj < 4; jj++)
        split1(acc2[i][jj] * inv, hv[jj], lv[jj]);
      const size_t ptr = obase + (size_t)(r0 + i) * D + m0;
      *(__nv_bfloat162*)&Oh[ptr]     = __nv_bfloat162(hv[0], hv[1]);
      *(__nv_bfloat162*)&Oh[ptr + 2] = __nv_bfloat162(hv[2], hv[3]);
      *(__nv_bfloat162*)&Ol[ptr]     = __nv_bfloat162(lv[0], lv[1]);
      *(__nv_bfloat162*)&Ol[ptr + 2] = __nv_bfloat162(lv[2], lv[3]);
    }
  }
}

// ---------------- launch ----------------
extern "C" void kernel_launch(void* const* d_in, const int* in_sizes, int n_in,
                              void* d_out, int out_size)
{
  (void)in_sizes; (void)n_in; (void)out_size;
  const float* x      = (const float*)d_in[0];
  const float* ln_g   = (const float*)d_in[1];
  const float* ln_b   = (const float*)d_in[2];
  const float* qkv_w  = (const float*)d_in[3];
  const float* qkv_b  = (const float*)d_in[4];
  const float* gate_w = (const float*)d_in[5];
  const float* gate_b = (const float*)d_in[6];
  const float* proj_w = (const float*)d_in[7];
  const float* proj_b = (const float*)d_in[8];
  float* out = (float*)d_out;

  float *gate, *qkv, *Q, *K, *V, *lkv, *lks, *Spre, *zpre;
  __nv_bfloat16 *xh, *xl, *xnh, *xnl, *ah, *al, *qwh, *qwl, *gwh, *gwl, *pwh, *pwl;
  cudaGetSymbolAddress((void**)&gate, g_gate);
  cudaGetSymbolAddress((void**)&qkv,  g_qkv);
  cudaGetSymbolAddress((void**)&Q,    g_Q);
  cudaGetSymbolAddress((void**)&K,    g_K);
  cudaGetSymbolAddress((void**)&V,    g_V);
  cudaGetSymbolAddress((void**)&lkv,  g_lkv);
  cudaGetSymbolAddress((void**)&lks,  g_lks);
  cudaGetSymbolAddress((void**)&Spre, g_Spre);
  cudaGetSymbolAddress((void**)&zpre, g_zpre);
  cudaGetSymbolAddress((void**)&xh,   g_xh);
  cudaGetSymbolAddress((void**)&xl,   g_xl);
  cudaGetSymbolAddress((void**)&xnh,  g_xnh);
  cudaGetSymbolAddress((void**)&xnl,  g_xnl);
  cudaGetSymbolAddress((void**)&ah,   g_ah);
  cudaGetSymbolAddress((void**)&al,   g_al);
  cudaGetSymbolAddress((void**)&qwh,  g_qwh);
  cudaGetSymbolAddress((void**)&qwl,  g_qwl);
  cudaGetSymbolAddress((void**)&gwh,  g_gwh);
  cudaGetSymbolAddress((void**)&gwl,  g_gwl);
  cudaGetSymbolAddress((void**)&pwh,  g_pwh);
  cudaGetSymbolAddress((void**)&pwl,  g_pwl);

  const int CHUNK_SMEM = 2 * CS * DH * 4;
  const int ATTN_SMEM  = (128*65 + 128*65 + 128*130 + 64*65 + 64 + 128 + 128*16) * 4;
  const int GEMM_SMEM  = 2 * STAGE;   // 81920
  cudaFuncSetAttribute(chunk_sums_kernel, cudaFuncAttributeMaxDynamicSharedMemorySize, CHUNK_SMEM);
  cudaFuncSetAttribute(attn_kernel,       cudaFuncAttributeMaxDynamicSharedMemorySize, ATTN_SMEM);
  cudaFuncSetAttribute(hmma_gemm_kernel<0>, cudaFuncAttributeMaxDynamicSharedMemorySize, GEMM_SMEM);
  cudaFuncSetAttribute(hmma_gemm_kernel<1>, cudaFuncAttributeMaxDynamicSharedMemorySize, GEMM_SMEM);

  // splits
  split_kernel<<<(T*D/4 + 255)/256, 256>>>(x,      xh,  xl,  T*D/4);
  split_kernel<<<(3*D*D/4 + 255)/256, 256>>>(qkv_w, qwh, qwl, 3*D*D/4);
  split_kernel<<<(D*D/4 + 255)/256, 256>>>(gate_w,  gwh, gwl, D*D/4);
  split_kernel<<<(D*D/4 + 255)/256, 256>>>(proj_w,  pwh, pwl, D*D/4);

  ln_kernel<<<T, 256>>>(x, ln_g, ln_b, xnh, xnl);

  hmma_gemm_kernel<1><<<dim3(D/128, T/128), 256, GEMM_SMEM>>>(xh, xl, gwh, gwl, gate_b, gate, D);
  hmma_gemm_kernel<0><<<dim3(3*D/128, T/128), 256, GEMM_SMEM>>>(xnh, xnl, qwh, qwl, qkv_b, qkv, 3*D);

  prep_kernel<<<T, 256>>>(gate, qkv, Q, K, V);
  chunk_sums_kernel<<<H * NC, 256, CHUNK_SMEM>>>(K, V, lkv, lks);
  scan_kernel<<<H, 256>>>(lkv, lks, Spre, zpre);
  attn_kernel<<<H * NC, 256, ATTN_SMEM>>>(Q, K, V, Spre, zpre, ah, al);

  hmma_gemm_kernel<0><<<dim3(D/128, T/128), 256, GEMM_SMEM>>>(ah, al, pwh, pwl, proj_b, out, D);
}

// round 4
// speedup vs baseline: 1.7390x; 1.0178x over previous
#include <cuda_runtime.h>
#include <cuda_bf16.h>
#include <cstdint>
#include <math.h>

#define T 2048
#define D 1024
#define H 16
#define DH 64
#define NC 16
#define CS 128
#define GK 1024

// ---------------- scratch (no allocations allowed) ----------------
__device__ float g_gate[T*D];
__device__ float g_qkv[T*3*D];
__device__ float g_Q[T*D];
__device__ float g_K[T*D];
__device__ float g_V[T*D];
__device__ float g_lkv[H*NC*DH*DH];
__device__ float g_lks[H*NC*DH];
__device__ float g_Spre[H*NC*DH*DH];
__device__ float g_zpre[H*NC*DH];

// bf16 hi/lo splits
__device__ __nv_bfloat16 g_xh[T*D],  g_xl[T*D];
__device__ __nv_bfloat16 g_xnh[T*D], g_xnl[T*D];
__device__ __nv_bfloat16 g_ah[T*D],  g_al[T*D];
__device__ __nv_bfloat16 g_qwh[3*D*D], g_qwl[3*D*D];
__device__ __nv_bfloat16 g_gwh[D*D],   g_gwl[D*D];
__device__ __nv_bfloat16 g_pwh[D*D],   g_pwl[D*D];

// ---------------- helpers ----------------
__device__ __forceinline__ uint32_t smem_u32(const void* p){
  uint32_t a;
  asm("{ .reg .u64 t; cvta.to.shared.u64 t, %1; cvt.u32.u64 %0, t; }" : "=r"(a) : "l"(p));
  return a;
}
__device__ __forceinline__ float elu1f(float x){ return x > 0.f ? x + 1.f : expf(x); }
__device__ __forceinline__ void split1(float v, __nv_bfloat16 &h, __nv_bfloat16 &l){
  h = __float2bfloat16(v);
  l = __float2bfloat16(v - __bfloat162float(h));
}

__device__ __forceinline__ void ldsm_x4(uint32_t* r, uint32_t addr){
  asm volatile("ldmatrix.sync.aligned.m8n8.x4.shared.b16 {%0,%1,%2,%3}, [%4];"
    : "=r"(r[0]), "=r"(r[1]), "=r"(r[2]), "=r"(r[3]) : "r"(addr));
}
__device__ __forceinline__ void mma_bf16(float* c, const uint32_t* a, const uint32_t* b){
  asm volatile(
    "mma.sync.aligned.m16n8k16.row.col.f32.bf16.bf16.f32 "
    "{%0,%1,%2,%3},{%4,%5,%6,%7},{%8,%9},{%0,%1,%2,%3};"
    : "+f"(c[0]), "+f"(c[1]), "+f"(c[2]), "+f"(c[3])
    : "r"(a[0]), "r"(a[1]), "r"(a[2]), "r"(a[3]), "r"(b[0]), "r"(b[1]));
}
__device__ __forceinline__ void cp16(uint32_t smem, const void* gmem){
  asm volatile("cp.async.cg.shared.global [%0], [%1], 16;" :: "r"(smem), "l"(gmem));
}
__device__ __forceinline__ void cp_commit(){
  asm volatile("cp.async.commit_group;" ::: "memory");
}
template<int N>
__device__ __forceinline__ void cp_wait(){
  asm volatile("cp.async.wait_group %0;" :: "n"(N) : "memory");
}

// ---------------- fused split fp32 -> bf16 hi/lo (x, qkv_w, gate_w, proj_w) ----------------
#define X4 (T*D/4)
#define Q4 (3*D*D/4)
#define G4 (D*D/4)
#define P4 (D*D/4)
__global__ void split_all_kernel(const float* __restrict__ x, const float* __restrict__ qw,
                                 const float* __restrict__ gw, const float* __restrict__ pw,
                                 __nv_bfloat16* __restrict__ xh, __nv_bfloat16* __restrict__ xl,
                                 __nv_bfloat16* __restrict__ qwh, __nv_bfloat16* __restrict__ qwl,
                                 __nv_bfloat16* __restrict__ gwh, __nv_bfloat16* __restrict__ gwl,
                                 __nv_bfloat16* __restrict__ pwh, __nv_bfloat16* __restrict__ pwl)
{
  int i = blockIdx.x * 256 + threadIdx.x;
  const float* src; __nv_bfloat16 *hp, *lp; int j;
  if (i < X4){ src = x; hp = xh; lp = xl; j = i; }
  else if (i < X4 + Q4){ src = qw; hp = qwh; lp = qwl; j = i - X4; }
  else if (i < X4 + Q4 + G4){ src = gw; hp = gwh; lp = gwl; j = i - (X4 + Q4); }
  else { src = pw; hp = pwh; lp = pwl; j = i - (X4 + Q4 + G4); }
  float4 v = ((const float4*)src)[j];
  __nv_bfloat16 hv[4], lv[4];
  split1(v.x, hv[0], lv[0]); split1(v.y, hv[1], lv[1]);
  split1(v.z, hv[2], lv[2]); split1(v.w, hv[3], lv[3]);
  ((__nv_bfloat162*)hp)[j*2]   = __nv_bfloat162(hv[0], hv[1]);
  ((__nv_bfloat162*)hp)[j*2+1] = __nv_bfloat162(hv[2], hv[3]);
  ((__nv_bfloat162*)lp)[j*2]   = __nv_bfloat162(lv[0], lv[1]);
  ((__nv_bfloat162*)lp)[j*2+1] = __nv_bfloat162(lv[2], lv[3]);
}

// ---------------- LayerNorm -> bf16 hi/lo ----------------
__global__ void ln_kernel(const float* __restrict__ x, const float* __restrict__ g,
                          const float* __restrict__ b,
                          __nv_bfloat16* __restrict__ xnh, __nv_bfloat16* __restrict__ xnl)
{
  __shared__ float red[16];
  const int t = blockIdx.x;
  const int i = threadIdx.x;
  float4 xv = ((const float4*)(x + (size_t)t*D))[i];
  float s  = xv.x + xv.y + xv.z + xv.w;
  float s2 = xv.x*xv.x + xv.y*xv.y + xv.z*xv.z + xv.w*xv.w;
  const int lane = i & 31, w = i >> 5;
  #pragma unroll
  for (int o = 16; o; o >>= 1){
    s  += __shfl_xor_sync(0xffffffffu, s,  o);
    s2 += __shfl_xor_sync(0xffffffffu, s2, o);
  }
  if (lane == 0){ red[w] = s; red[8+w] = s2; }
  __syncthreads();
  if (i == 0){
    float a = 0.f, c = 0.f;
    #pragma unroll
    for (int k = 0; k < 8; k++){ a += red[k]; c += red[8+k]; }
    red[0] = a; red[8] = c;
  }
  __syncthreads();
  const float mu   = red[0] * (1.f / D);
  const float var  = red[8] * (1.f / D) - mu * mu;
  const float rstd = rsqrtf(var + 1e-5f);
  float4 gv = ((const float4*)g)[i];
  float4 bv = ((const float4*)b)[i];
  float o[4];
  o[0] = (xv.x - mu) * rstd * gv.x + bv.x;
  o[1] = (xv.y - mu) * rstd * gv.y + bv.y;
  o[2] = (xv.z - mu) * rstd * gv.z + bv.z;
  o[3] = (xv.w - mu) * rstd * gv.w + bv.w;
  __nv_bfloat16 hv[4], lv[4];
  #pragma unroll
  for (int k = 0; k < 4; k++) split1(o[k], hv[k], lv[k]);
  const size_t base2 = ((size_t)t*D >> 1) + i*2;
  ((__nv_bfloat162*)xnh)[base2]   = __nv_bfloat162(hv[0], hv[1]);
  ((__nv_bfloat162*)xnh)[base2+1] = __nv_bfloat162(hv[2], hv[3]);
  ((__nv_bfloat162*)xnl)[base2]   = __nv_bfloat162(lv[0], lv[1]);
  ((__nv_bfloat162*)xnl)[base2+1] = __nv_bfloat162(lv[2], lv[3]);
}

// ---------------- HMMA GEMM: C[2048,N] = A[2048,1024] @ B[N,1024]^T ----------------
// 3-term bf16 split: C = Ah Bh + Ah Bl + Al Bh (fp32 accum).
// Block tile 128x128, BK=32, 8 warps of 64x32, 4-stage cp.async ring, 1 sync/ktile.
#define PITCH 80          // bytes per SMEM row (64B data + 16B pad)
#define ARR   (128*PITCH) // 10240 B per array
#define STAGE (4*ARR)     // Ah,Al,Bh,Bl = 40960 B
#define NRING 4
#define NKT   (GK/32)     // 32 k-tiles
#define GEMM_SMEM (NRING*STAGE)  // 163840 B

struct GArgs {
  const __nv_bfloat16 *Ah, *Al, *Bh, *Bl;
  const float* bias;
  float* C;
  int N;
  int sig;
};

__device__ __forceinline__ void gemm_load_stage(uint32_t sbase,
    const __nv_bfloat16* Ah, const __nv_bfloat16* Al,
    const __nv_bfloat16* Bh, const __nv_bfloat16* Bl,
    int kt, int tid)
{
  const int koff = kt * 32;
  const __nv_bfloat16* srcs[4] = {Ah, Al, Bh, Bl};
  #pragma unroll
  for (int arr = 0; arr < 4; arr++){
    const __nv_bfloat16* s = srcs[arr] + koff;
    #pragma unroll
    for (int it = 0; it < 2; it++){
      const int within = tid + it * 256;      // 0..511
      const int row = within >> 2, c16 = within & 3;
      cp16(sbase + arr*ARR + row*PITCH + c16*16,
           s + (size_t)row * GK + c16*8);
    }
  }
}

__global__ void __launch_bounds__(256, 1)
hmma_gemm_dual(GArgs g0, GArgs g1, int split)
{
  extern __shared__ __align__(128) char sm[];
  const uint32_t sb = smem_u32(sm);
  const int tid = threadIdx.x;
  const int wid = tid >> 5, lane = tid & 31;
  const int wm = wid & 1, wn = wid >> 1;
  const int m0w = wm * 64, n0w = wn * 32;

  const bool first = ((int)blockIdx.x < split);
  const GArgs ga = first ? g0 : g1;
  const int bxn = first ? (int)blockIdx.x : (int)blockIdx.x - split;
  const int bn0 = bxn << 7, bm0 = blockIdx.y << 7;

  const __nv_bfloat16* pAh = ga.Ah + (size_t)bm0 * GK;
  const __nv_bfloat16* pAl = ga.Al + (size_t)bm0 * GK;
  const __nv_bfloat16* pBh = ga.Bh + (size_t)bn0 * GK;
  const __nv_bfloat16* pBl = ga.Bl + (size_t)bn0 * GK;

  float acc[4][4][4];
  #pragma unroll
  for (int i = 0; i < 4; i++)
    #pragma unroll
    for (int j = 0; j < 4; j++)
      #pragma unroll
      for (int q = 0; q < 4; q++) acc[i][j][q] = 0.f;

  // ldmatrix per-lane offsets
  const int rowA = lane & 15;
  const uint32_t colA = (lane >> 4) << 4;                 // 0 or 16 bytes
  const int rowB = (lane & 7) + (((lane >> 4) & 1) << 3); // 0..15
  const uint32_t colB = ((lane >> 3) & 1) << 4;           // 0 or 16 bytes

  // prime 3 stages of the ring
  gemm_load_stage(sb + 0*STAGE, pAh, pAl, pBh, pBl, 0, tid); cp_commit();
  gemm_load_stage(sb + 1*STAGE, pAh, pAl, pBh, pBl, 1, tid); cp_commit();
  gemm_load_stage(sb + 2*STAGE, pAh, pAl, pBh, pBl, 2, tid); cp_commit();

  for (int kt = 0; kt < NKT; kt++){
    cp_wait<2>();
    __syncthreads();

    // prefetch stage kt+3 (overwrites ring slot of kt-1; all readers passed the barrier)
    if (kt + 3 < NKT)
      gemm_load_stage(sb + ((kt + 3) & (NRING-1)) * STAGE, pAh, pAl, pBh, pBl, kt + 3, tid);
    cp_commit();

    const uint32_t st = sb + (kt & (NRING-1)) * STAGE;
    const uint32_t aBaseH = st           + (m0w + rowA) * PITCH + colA;
    const uint32_t aBaseL = st + ARR     + (m0w + rowA) * PITCH + colA;
    const uint32_t bBaseH = st + 2*ARR   + (n0w + rowB) * PITCH + colB;
    const uint32_t bBaseL = st + 3*ARR   + (n0w + rowB) * PITCH + colB;

    #pragma unroll
    for (int ks = 0; ks < 2; ks++){
      const uint32_t kb = ks * 32;
      uint32_t a_h[4][4], a_l[4][4], b_h[4][2], b_l[4][2];
      #pragma unroll
      for (int mi = 0; mi < 4; mi++){
        ldsm_x4(a_h[mi], aBaseH + mi*16*PITCH + kb);
        ldsm_x4(a_l[mi], aBaseL + mi*16*PITCH + kb);
      }
      #pragma unroll
      for (int p = 0; p < 2; p++){
        uint32_t r[4];
        ldsm_x4(r, bBaseH + p*16*PITCH + kb);
        b_h[2*p][0] = r[0]; b_h[2*p][1] = r[1];
        b_h[2*p+1][0] = r[2]; b_h[2*p+1][1] = r[3];
        ldsm_x4(r, bBaseL + p*16*PITCH + kb);
        b_l[2*p][0] = r[0]; b_l[2*p][1] = r[1];
        b_l[2*p+1][0] = r[2]; b_l[2*p+1][1] = r[3];
      }
      // term 1: Ah*Bh
      #pragma unroll
      for (int mi = 0; mi < 4; mi++)
        #pragma unroll
        for (int nj = 0; nj < 4; nj++)
          mma_bf16(acc[mi][nj], a_h[mi], b_h[nj]);
      // term 2: Ah*Bl
      #pragma unroll
      for (int mi = 0; mi < 4; mi++)
        #pragma unroll
        for (int nj = 0; nj < 4; nj++)
          mma_bf16(acc[mi][nj], a_h[mi], b_l[nj]);
      // term 3: Al*Bh
      #pragma unroll
      for (int mi = 0; mi < 4; mi++)
        #pragma unroll
        for (int nj = 0; nj < 4; nj++)
          mma_bf16(acc[mi][nj], a_l[mi], b_h[nj]);
    }
  }

  // epilogue
  const int g = lane >> 2, t4 = lane & 3;
  #pragma unroll
  for (int mi = 0; mi < 4; mi++){
    #pragma unroll
    for (int nj = 0; nj < 4; nj++){
      const int row = bm0 + m0w + mi*16 + g;
      const int col = bn0 + n0w + nj*8 + t4*2;
      float b0 = ga.bias[col], b1 = ga.bias[col+1];
      float o0 = acc[mi][nj][0] + b0, o1 = acc[mi][nj][1] + b1;
      float o2 = acc[mi][nj][2] + b0, o3 = acc[mi][nj][3] + b1;
      if (ga.sig){
        o0 = 1.f / (1.f + expf(-o0)); o1 = 1.f / (1.f + expf(-o1));
        o2 = 1.f / (1.f + expf(-o2)); o3 = 1.f / (1.f + expf(-o3));
      }
      *(float2*)(ga.C + (size_t)row * ga.N + col)       = make_float2(o0, o1);
      *(float2*)(ga.C + (size_t)(row + 8) * ga.N + col) = make_float2(o2, o3);
    }
  }
}

// ---------------- gate-normalize + apply + elu+1 + head split ----------------
__global__ void prep_kernel(const float* __restrict__ gate, const float* __restrict__ qkv,
                            float* __restrict__ Q, float* __restrict__ K, float* __restrict__ V)
{
  __shared__ float red[8];
  const int t = blockIdx.x, i = threadIdx.x;
  float4 gv = ((const float4*)(gate + (size_t)t*D))[i];
  float s = gv.x + gv.y + gv.z + gv.w;
  const int lane = i & 31, w = i >> 5;
  #pragma unroll
  for (int o = 16; o; o >>= 1) s += __shfl_xor_sync(0xffffffffu, s, o);
  if (lane == 0) red[w] = s;
  __syncthreads();
  if (i == 0){
    float a = 0.f;
    #pragma unroll
    for (int k = 0; k < 8; k++) a += red[k];
    red[0] = a;
  }
  __syncthreads();
  const float inv = 1.f / (red[0] * (1.f / D) + 1e-5f);

  const float4* qrow = (const float4*)(qkv + (size_t)t * 3 * D);
  float4 qv = qrow[i], kv = qrow[i + 256], vv = qrow[i + 512];
  float4 qo, ko;
  qo.x = elu1f(qv.x * gv.x * inv); qo.y = elu1f(qv.y * gv.y * inv);
  qo.z = elu1f(qv.z * gv.z * inv); qo.w = elu1f(qv.w * gv.w * inv);
  ko.x = elu1f(kv.x * gv.x * inv); ko.y = elu1f(kv.y * gv.y * inv);
  ko.z = elu1f(kv.z * gv.z * inv); ko.w = elu1f(kv.w * gv.w * inv);

  const int h = i >> 4;
  const int dh = (i & 15) << 2;
  const size_t b4 = ((size_t)(h * T + t) * DH + dh) >> 2;
  ((float4*)Q)[b4] = qo;
  ((float4*)K)[b4] = ko;
  ((float4*)V)[b4] = vv;
}

// ---------------- per-(head,chunk) local K^T V and K column sums ----------------
__global__ void chunk_sums_kernel(const float* __restrict__ Kg, const float* __restrict__ Vg,
                                  float* __restrict__ lkv, float* __restrict__ lks)
{
  extern __shared__ float smf[];
  float* Ks = smf;
  float* Vs = smf + CS * DH;
  const int hc = blockIdx.x, h = hc >> 4, c = hc & 15;
  const float* Kc = Kg + (size_t)(h * T + c * CS) * DH;
  const float* Vc = Vg + (size_t)(h * T + c * CS) * DH;
  const int tid = threadIdx.x;
  for (int idx = tid; idx < CS * DH / 4; idx += 256){
    ((float4*)Ks)[idx] = ((const float4*)Kc)[idx];
    ((float4*)Vs)[idx] = ((const float4*)Vc)[idx];
  }
  __syncthreads();

  const int m = tid & 63;
  const int dg = tid >> 6;
  float acc[16];
  #pragma unroll
  for (int i = 0; i < 16; i++) acc[i] = 0.f;
  for (int tt = 0; tt < CS; tt++){
    const float vv = Vs[tt * DH + m];
    #pragma unroll
    for (int i = 0; i < 16; i++)
      acc[i] += Ks[tt * DH + dg * 16 + i] * vv;
  }
  float* dst = lkv + (size_t)hc * DH * DH;
  #pragma unroll
  for (int i = 0; i < 16; i++)
    dst[(dg * 16 + i) * DH + m] = acc[i];

  if (tid < DH){
    float s = 0.f;
    for (int tt = 0; tt < CS; tt++) s += Ks[tt * DH + tid];
    lks[(size_t)hc * DH + tid] = s;
  }
}

// ---------------- exclusive prefix over chunks ----------------
__global__ void scan_kernel(const float* __restrict__ lkv, const float* __restrict__ lks,
                            float* __restrict__ Spre, float* __restrict__ zpre)
{
  const int h = blockIdx.x;
  for (int idx = threadIdx.x; idx < DH * DH; idx += blockDim.x){
    float acc = 0.f;
    for (int c = 0; c < NC; c++){
      const size_t o = (size_t)(h * NC + c) * DH * DH + idx;
      Spre[o] = acc;
      acc += lkv[o];
    }
  }
  for (int idx = threadIdx.x; idx < DH; idx += blockDim.x){
    float acc = 0.f;
    for (int c = 0; c < NC; c++){
      const size_t o = (size_t)(h * NC + c) * DH + idx;
      zpre[o] = acc;
      acc += lks[o];
    }
  }
}

// ---------------- per-(head,chunk) attention output -> bf16 hi/lo ----------------
__global__ void attn_kernel(const float* __restrict__ Qg, const float* __restrict__ Kg,
                            const float* __restrict__ Vg, const float* __restrict__ Spre,
                            const float* __restrict__ zpre,
                            __nv_bfloat16* __restrict__ Oh, __nv_bfloat16* __restrict__ Ol)
{
  extern __shared__ float smf[];
  float* Qs  = smf;              // 128 x 65
  float* Ks  = Qs  + 128 * 65;   // 128 x 65 (later reused for V)
  float* As  = Ks  + 128 * 65;   // 128 x 130
  float* Sp  = As  + 128 * 130;  // 64 x 65
  float* zp  = Sp  + 64 * 65;    // 64
  float* dn  = zp  + 64;         // 128
  float* dnp = dn  + 128;        // 128 x 16

  const int hc = blockIdx.x, h = hc >> 4, c = hc & 15;
  const int tid = threadIdx.x;
  const float* Qc = Qg + (size_t)(h * T + c * CS) * DH;
  const float* Kc = Kg + (size_t)(h * T + c * CS) * DH;

  for (int idx = tid; idx < CS * DH / 4; idx += 256){
    const int r = idx >> 4, c4 = (idx & 15) << 2;
    float4 q = ((const float4*)Qc)[idx];
    float4 k = ((const float4*)Kc)[idx];
    float* qd = Qs + r * 65 + c4;
    qd[0] = q.x; qd[1] = q.y; qd[2] = q.z; qd[3] = q.w;
    float* kd = Ks + r * 65 + c4;
    kd[0] = k.x; kd[1] = k.y; kd[2] = k.z; kd[3] = k.w;
  }
  const float* SpG = Spre + (size_t)hc * DH * DH;
  for (int idx = tid; idx < DH * DH; idx += 256)
    Sp[(idx >> 6) * 65 + (idx & 63)] = SpG[idx];
  if (tid < 64) zp[tid] = zpre[(size_t)hc * DH + tid];
  __syncthreads();

  if (tid < 128){
    float s = 0.f;
    #pragma unroll
    for (int d = 0; d < 64; d++) s += Qs[tid * 65 + d] * zp[d];
    dn[tid] = s;
  }
  __syncthreads();

  const int tx = tid & 15, ty = tid >> 4;
  {
    float acc[8][8];
    #pragma unroll
    for (int i = 0; i < 8; i++)
      #pragma unroll
      for (int j = 0; j < 8; j++) acc[i][j] = 0.f;
    for (int d = 0; d < 64; d++){
      float a[8], b[8];
      #pragma unroll
      for (int i = 0; i < 8; i++) a[i] = Qs[(ty * 8 + i) * 65 + d];
      #pragma unroll
      for (int j = 0; j < 8; j++) b[j] = Ks[(tx * 8 + j) * 65 + d];
      #pragma unroll
      for (int i = 0; i < 8; i++)
        #pragma unroll
        for (int j = 0; j < 8; j++)
          acc[i][j] += a[i] * b[j];
    }
    #pragma unroll
    for (int i = 0; i < 8; i++){
      const int r = ty * 8 + i;
      float rs = 0.f;
      #pragma unroll
      for (int j = 0; j < 8; j++){
        const int s_ = tx * 8 + j;
        const float v = (s_ <= r) ? acc[i][j] : 0.f;
        As[r * 130 + s_] = v;
        rs += v;
      }
      dnp[r * 16 + tx] = rs;
    }
  }
  __syncthreads();

  {
    const float* Vc = Vg + (size_t)(h * T + c * CS) * DH;
    for (int idx = tid; idx < CS * DH / 4; idx += 256){
      const int r = idx >> 4, c4 = (idx & 15) << 2;
      float4 v = ((const float4*)Vc)[idx];
      float* vd = Ks + r * 65 + c4;
      vd[0] = v.x; vd[1] = v.y; vd[2] = v.z; vd[3] = v.w;
    }
    if (tid < 128){
      float s = dn[tid];
      #pragma unroll
      for (int xx = 0; xx < 16; xx++) s += dnp[tid * 16 + xx];
      dn[tid] = s + 1e-5f;
    }
  }
  __syncthreads();

  {
    float acc2[8][4];
    #pragma unroll
    for (int i = 0; i < 8; i++)
      #pragma unroll
      for (int j = 0; j < 4; j++) acc2[i][j] = 0.f;
    const int m0 = tx * 4, r0 = ty * 8;
    for (int s = 0; s < 128; s++){
      float vv[4];
      #pragma unroll
      for (int jj = 0; jj < 4; jj++) vv[jj] = Ks[s * 65 + m0 + jj];
      #pragma unroll
      for (int i = 0; i < 8; i++){
        const float av = As[(r0 + i) * 130 + s];
        #pragma unroll
        for (int jj = 0; jj < 4; jj++) acc2[i][jj] += av * vv[jj];
      }
    }
    for (int d = 0; d < 64; d++){
      float sp[4];
      #pragma unroll
      for (int jj = 0; jj < 4; jj++) sp[jj] = Sp[d * 65 + m0 + jj];
      #pragma unroll
      for (int i = 0; i < 8; i++){
        const float qv = Qs[(r0 + i) * 65 + d];
        #pragma unroll
        for (int jj = 0; jj < 4; jj++) acc2[i][jj] += qv * sp[jj];
      }
    }
    const size_t obase = (size_t)(c * CS) * D + h * DH;
    #pragma unroll
    for (int i = 0; i < 8; i++){
      const float inv = 1.f / dn[r0 + i];
      __nv_bfloat16 hv[4], lv[4];
      #pragma unroll
      for (int jj = 0; jj < 4; jj++)
        split1(acc2[i][jj] * inv, hv[jj], lv[jj]);
      const size_t ptr = obase + (size_t)(r0 + i) * D + m0;
      *(__nv_bfloat162*)&Oh[ptr]     = __nv_bfloat162(hv[0], hv[1]);
      *(__nv_bfloat162*)&Oh[ptr + 2] = __nv_bfloat162(hv[2], hv[3]);
      *(__nv_bfloat162*)&Ol[ptr]     = __nv_bfloat162(lv[0], lv[1]);
      *(__nv_bfloat162*)&Ol[ptr + 2] = __nv_bfloat162(lv[2], lv[3]);
    }
  }
}

// ---------------- launch ----------------
extern "C" void kernel_launch(void* const* d_in, const int* in_sizes, int n_in,
                              void* d_out, int out_size)
{
  (void)in_sizes; (void)n_in; (void)out_size;
  const float* x      = (const float*)d_in[0];
  const float* ln_g   = (const float*)d_in[1];
  const float* ln_b   = (const float*)d_in[2];
  const float* qkv_w  = (const float*)d_in[3];
  const float* qkv_b  = (const float*)d_in[4];
  const float* gate_w = (const float*)d_in[5];
  const float* gate_b = (const float*)d_in[6];
  const float* proj_w = (const float*)d_in[7];
  const float* proj_b = (const float*)d_in[8];
  float* out = (float*)d_out;

  float *gate, *qkv, *Q, *K, *V, *lkv, *lks, *Spre, *zpre;
  __nv_bfloat16 *xh, *xl, *xnh, *xnl, *ah, *al, *qwh, *qwl, *gwh, *gwl, *pwh, *pwl;
  cudaGetSymbolAddress((void**)&gate, g_gate);
  cudaGetSymbolAddress((void**)&qkv,  g_qkv);
  cudaGetSymbolAddress((void**)&Q,    g_Q);
  cudaGetSymbolAddress((void**)&K,    g_K);
  cudaGetSymbolAddress((void**)&V,    g_V);
  cudaGetSymbolAddress((void**)&lkv,  g_lkv);
  cudaGetSymbolAddress((void**)&lks,  g_lks);
  cudaGetSymbolAddress((void**)&Spre, g_Spre);
  cudaGetSymbolAddress((void**)&zpre, g_zpre);
  cudaGetSymbolAddress((void**)&xh,   g_xh);
  cudaGetSymbolAddress((void**)&xl,   g_xl);
  cudaGetSymbolAddress((void**)&xnh,  g_xnh);
  cudaGetSymbolAddress((void**)&xnl,  g_xnl);
  cudaGetSymbolAddress((void**)&ah,   g_ah);
  cudaGetSymbolAddress((void**)&al,   g_al);
  cudaGetSymbolAddress((void**)&qwh,  g_qwh);
  cudaGetSymbolAddress((void**)&qwl,  g_qwl);
  cudaGetSymbolAddress((void**)&gwh,  g_gwh);
  cudaGetSymbolAddress((void**)&gwl,  g_gwl);
  cudaGetSymbolAddress((void**)&pwh,  g_pwh);
  cudaGetSymbolAddress((void**)&pwl,  g_pwl);

  const int CHUNK_SMEM = 2 * CS * DH * 4;
  const int ATTN_SMEM  = (128*65 + 128*65 + 128*130 + 64*65 + 64 + 128 + 128*16) * 4;
  cudaFuncSetAttribute(chunk_sums_kernel, cudaFuncAttributeMaxDynamicSharedMemorySize, CHUNK_SMEM);
  cudaFuncSetAttribute(attn_kernel,       cudaFuncAttributeMaxDynamicSharedMemorySize, ATTN_SMEM);
  cudaFuncSetAttribute(hmma_gemm_dual,    cudaFuncAttributeMaxDynamicSharedMemorySize, GEMM_SMEM);

  // fused splits (x, qkv_w, gate_w, proj_w)
  split_all_kernel<<<(X4 + Q4 + G4 + P4) / 256, 256>>>(
      x, qkv_w, gate_w, proj_w, xh, xl, qwh, qwl, gwh, gwl, pwh, pwl);

  ln_kernel<<<T, 256>>>(x, ln_g, ln_b, xnh, xnl);

  // merged gate + qkv GEMM launch
  GArgs gateArgs = { xh,  xl,  gwh, gwl, gate_b, gate, D,     1 };
  GArgs qkvArgs  = { xnh, xnl, qwh, qwl, qkv_b,  qkv,  3 * D, 0 };
  hmma_gemm_dual<<<dim3(8 + 24, T / 128), 256, GEMM_SMEM>>>(gateArgs, qkvArgs, 8);

  prep_kernel<<<T, 256>>>(gate, qkv, Q, K, V);
  chunk_sums_kernel<<<H * NC, 256, CHUNK_SMEM>>>(K, V, lkv, lks);
  scan_kernel<<<H, 256>>>(lkv, lks, Spre, zpre);
  attn_kernel<<<H * NC, 256, ATTN_SMEM>>>(Q, K, V, Spre, zpre, ah, al);

  GArgs projArgs = { ah, al, pwh, pwl, proj_b, out, D, 0 };
  hmma_gemm_dual<<<dim3(8, T / 128), 256, GEMM_SMEM>>>(projArgs, projArgs, 8);
}